// round 1
// baseline (speedup 1.0000x reference)
#include <cuda_runtime.h>

static constexpr int B_ = 32;
static constexpr int H_ = 8;
static constexpr int N_ = 512;
static constexpr int C_ = 64;
static constexpr int NS_ = 16;   // scalar channels
static constexpr int NV_ = 12;   // 4-vector channels
static constexpr long QKV_ELEMS = (long)B_ * H_ * N_ * C_;   // 8,388,608
static constexpr int  FR_ELEMS  = B_ * N_ * 16;              // 262,144

// Scratch (static device allocations are allowed)
__device__ float g_q[QKV_ELEMS];
__device__ float g_k[QKV_ELEMS];
__device__ float g_v[QKV_ELEMS];
__device__ float g_inv[FR_ELEMS];
__device__ float g_linv[FR_ELEMS];

// ---------------------------------------------------------------------------
// Kernel 1: per-particle 4x4 inverse + eta-conjugated inverse
// ---------------------------------------------------------------------------
__global__ void frames_kernel(const float* __restrict__ lframes) {
    int idx = blockIdx.x * blockDim.x + threadIdx.x;
    if (idx >= B_ * N_) return;
    float m[16];
#pragma unroll
    for (int i = 0; i < 16; i++) m[i] = lframes[(long)idx * 16 + i];

    float inv[16];
    inv[0]  =  m[5]*m[10]*m[15] - m[5]*m[11]*m[14] - m[9]*m[6]*m[15] + m[9]*m[7]*m[14] + m[13]*m[6]*m[11] - m[13]*m[7]*m[10];
    inv[4]  = -m[4]*m[10]*m[15] + m[4]*m[11]*m[14] + m[8]*m[6]*m[15] - m[8]*m[7]*m[14] - m[12]*m[6]*m[11] + m[12]*m[7]*m[10];
    inv[8]  =  m[4]*m[9]*m[15]  - m[4]*m[11]*m[13] - m[8]*m[5]*m[15] + m[8]*m[7]*m[13] + m[12]*m[5]*m[11] - m[12]*m[7]*m[9];
    inv[12] = -m[4]*m[9]*m[14]  + m[4]*m[10]*m[13] + m[8]*m[5]*m[14] - m[8]*m[6]*m[13] - m[12]*m[5]*m[10] + m[12]*m[6]*m[9];
    inv[1]  = -m[1]*m[10]*m[15] + m[1]*m[11]*m[14] + m[9]*m[2]*m[15] - m[9]*m[3]*m[14] - m[13]*m[2]*m[11] + m[13]*m[3]*m[10];
    inv[5]  =  m[0]*m[10]*m[15] - m[0]*m[11]*m[14] - m[8]*m[2]*m[15] + m[8]*m[3]*m[14] + m[12]*m[2]*m[11] - m[12]*m[3]*m[10];
    inv[9]  = -m[0]*m[9]*m[15]  + m[0]*m[11]*m[13] + m[8]*m[1]*m[15] - m[8]*m[3]*m[13] - m[12]*m[1]*m[11] + m[12]*m[3]*m[9];
    inv[13] =  m[0]*m[9]*m[14]  - m[0]*m[10]*m[13] - m[8]*m[1]*m[14] + m[8]*m[2]*m[13] + m[12]*m[1]*m[10] - m[12]*m[2]*m[9];
    inv[2]  =  m[1]*m[6]*m[15]  - m[1]*m[7]*m[14]  - m[5]*m[2]*m[15] + m[5]*m[3]*m[14] + m[13]*m[2]*m[7]  - m[13]*m[3]*m[6];
    inv[6]  = -m[0]*m[6]*m[15]  + m[0]*m[7]*m[14]  + m[4]*m[2]*m[15] - m[4]*m[3]*m[14] - m[12]*m[2]*m[7]  + m[12]*m[3]*m[6];
    inv[10] =  m[0]*m[5]*m[15]  - m[0]*m[7]*m[13]  - m[4]*m[1]*m[15] + m[4]*m[3]*m[13] + m[12]*m[1]*m[7]  - m[12]*m[3]*m[5];
    inv[14] = -m[0]*m[5]*m[14]  + m[0]*m[6]*m[13]  + m[4]*m[1]*m[14] - m[4]*m[2]*m[13] - m[12]*m[1]*m[6]  + m[12]*m[2]*m[5];
    inv[3]  = -m[1]*m[6]*m[11]  + m[1]*m[7]*m[10]  + m[5]*m[2]*m[11] - m[5]*m[3]*m[10] - m[9]*m[2]*m[7]   + m[9]*m[3]*m[6];
    inv[7]  =  m[0]*m[6]*m[11]  - m[0]*m[7]*m[10]  - m[4]*m[2]*m[11] + m[4]*m[3]*m[10] + m[8]*m[2]*m[7]   - m[8]*m[3]*m[6];
    inv[11] = -m[0]*m[5]*m[11]  + m[0]*m[7]*m[9]   + m[4]*m[1]*m[11] - m[4]*m[3]*m[9]  - m[8]*m[1]*m[7]   + m[8]*m[3]*m[5];
    inv[15] =  m[0]*m[5]*m[10]  - m[0]*m[6]*m[9]   - m[4]*m[1]*m[10] + m[4]*m[2]*m[9]  + m[8]*m[1]*m[6]   - m[8]*m[2]*m[5];

    float det = m[0]*inv[0] + m[1]*inv[4] + m[2]*inv[8] + m[3]*inv[12];
    float d = 1.0f / det;
#pragma unroll
    for (int i = 0; i < 16; i++) {
        float val = inv[i] * d;
        g_inv[(long)idx * 16 + i] = val;
        int r = i >> 2, c = i & 3;
        float sgn = ((r == 0) == (c == 0)) ? 1.0f : -1.0f;  // eta_r * eta_c
        g_linv[(long)idx * 16 + i] = sgn * val;
    }
}

// ---------------------------------------------------------------------------
// Kernel 2: transform q (inv), k (eta*inv*eta), v (inv) into global frame
// One thread per (b,h,n). Scalars copy; vectors rotate by 4x4.
// ---------------------------------------------------------------------------
__global__ void transform_kernel(const float* __restrict__ q,
                                 const float* __restrict__ k,
                                 const float* __restrict__ v) {
    int idx = blockIdx.x * blockDim.x + threadIdx.x;
    if (idx >= B_ * H_ * N_) return;
    int n = idx % N_;
    int b = idx / (H_ * N_);
    long fb = (long)(b * N_ + n) * 16;
    float mi[16], ml[16];
#pragma unroll
    for (int i = 0; i < 16; i++) { mi[i] = g_inv[fb + i]; ml[i] = g_linv[fb + i]; }

    long base = (long)idx * C_;
    // scalar channels: straight copy
#pragma unroll
    for (int c4 = 0; c4 < 4; c4++) {
        reinterpret_cast<float4*>(g_q + base)[c4] = reinterpret_cast<const float4*>(q + base)[c4];
        reinterpret_cast<float4*>(g_k + base)[c4] = reinterpret_cast<const float4*>(k + base)[c4];
        reinterpret_cast<float4*>(g_v + base)[c4] = reinterpret_cast<const float4*>(v + base)[c4];
    }
    // vector channels
#pragma unroll
    for (int vi = 0; vi < NV_; vi++) {
        float4 x, y;
        x = reinterpret_cast<const float4*>(q + base + NS_)[vi];
        y.x = mi[0]*x.x + mi[1]*x.y + mi[2]*x.z + mi[3]*x.w;
        y.y = mi[4]*x.x + mi[5]*x.y + mi[6]*x.z + mi[7]*x.w;
        y.z = mi[8]*x.x + mi[9]*x.y + mi[10]*x.z + mi[11]*x.w;
        y.w = mi[12]*x.x + mi[13]*x.y + mi[14]*x.z + mi[15]*x.w;
        reinterpret_cast<float4*>(g_q + base + NS_)[vi] = y;

        x = reinterpret_cast<const float4*>(k + base + NS_)[vi];
        y.x = ml[0]*x.x + ml[1]*x.y + ml[2]*x.z + ml[3]*x.w;
        y.y = ml[4]*x.x + ml[5]*x.y + ml[6]*x.z + ml[7]*x.w;
        y.z = ml[8]*x.x + ml[9]*x.y + ml[10]*x.z + ml[11]*x.w;
        y.w = ml[12]*x.x + ml[13]*x.y + ml[14]*x.z + ml[15]*x.w;
        reinterpret_cast<float4*>(g_k + base + NS_)[vi] = y;

        x = reinterpret_cast<const float4*>(v + base + NS_)[vi];
        y.x = mi[0]*x.x + mi[1]*x.y + mi[2]*x.z + mi[3]*x.w;
        y.y = mi[4]*x.x + mi[5]*x.y + mi[6]*x.z + mi[7]*x.w;
        y.z = mi[8]*x.x + mi[9]*x.y + mi[10]*x.z + mi[11]*x.w;
        y.w = mi[12]*x.x + mi[13]*x.y + mi[14]*x.z + mi[15]*x.w;
        reinterpret_cast<float4*>(g_v + base + NS_)[vi] = y;
    }
}

// ---------------------------------------------------------------------------
// Kernel 3: flash attention (64-query tiles) + fused output frame transform.
// Block = 256 threads as 16x16; thread (ty,tx) owns 4x4 output block.
// Smem tiles stored transposed (QsT/KsT: [c][row]) for float4 LDS in GEMM1.
// ---------------------------------------------------------------------------
static constexpr int LDS_ = 68;  // 64 + 4 pad: float4-aligned, conflict-free
static constexpr int TILE_FLOATS = 64 * LDS_;

__global__ void __launch_bounds__(256) attn_kernel(const float* __restrict__ lframes,
                                                   float* __restrict__ out) {
    extern __shared__ float sm[];
    float* QsT = sm;                   // [c][r]
    float* KsT = sm + TILE_FLOATS;     // [c][j]
    float* Vs  = sm + 2 * TILE_FLOATS; // [k][c]
    float* Ps  = sm + 3 * TILE_FLOATS; // [r][k]

    const int t  = threadIdx.x;
    const int tx = t & 15;
    const int ty = t >> 4;
    const int qt = blockIdx.x;        // 0..7
    const int bh = blockIdx.y;        // 0..255
    const int b  = bh >> 3;           // H_ = 8
    const long base = (long)bh * N_ * C_;
    const int q0 = qt * 64;

    // Load Q tile transposed, pre-scaled by 1/sqrt(C)=0.125
    {
        const float scale = 0.125f;
#pragma unroll
        for (int rep = 0; rep < 4; rep++) {
            int id = rep * 256 + t;           // 0..1023 float4 slots
            int r  = id >> 4;
            int c4 = id & 15;
            float4 x = *reinterpret_cast<const float4*>(g_q + base + (long)(q0 + r) * C_ + c4 * 4);
            QsT[(c4 * 4 + 0) * LDS_ + r] = x.x * scale;
            QsT[(c4 * 4 + 1) * LDS_ + r] = x.y * scale;
            QsT[(c4 * 4 + 2) * LDS_ + r] = x.z * scale;
            QsT[(c4 * 4 + 3) * LDS_ + r] = x.w * scale;
        }
    }

    float o[4][4];
    float mrow[4], lrow[4];
#pragma unroll
    for (int i = 0; i < 4; i++) {
        mrow[i] = -1e30f; lrow[i] = 0.0f;
#pragma unroll
        for (int j = 0; j < 4; j++) o[i][j] = 0.0f;
    }

    for (int kc = 0; kc < 8; kc++) {
        const int k0 = kc * 64;
        __syncthreads();
        // Load K (transposed) and V (row-major) chunk
#pragma unroll
        for (int rep = 0; rep < 4; rep++) {
            int id = rep * 256 + t;
            int r  = id >> 4;
            int c4 = id & 15;
            float4 kx = *reinterpret_cast<const float4*>(g_k + base + (long)(k0 + r) * C_ + c4 * 4);
            KsT[(c4 * 4 + 0) * LDS_ + r] = kx.x;
            KsT[(c4 * 4 + 1) * LDS_ + r] = kx.y;
            KsT[(c4 * 4 + 2) * LDS_ + r] = kx.z;
            KsT[(c4 * 4 + 3) * LDS_ + r] = kx.w;
            float4 vx = *reinterpret_cast<const float4*>(g_v + base + (long)(k0 + r) * C_ + c4 * 4);
            *reinterpret_cast<float4*>(Vs + r * LDS_ + c4 * 4) = vx;
        }
        __syncthreads();

        // GEMM1: S = Q * K^T  (scaled Q)
        float s[4][4];
#pragma unroll
        for (int i = 0; i < 4; i++)
#pragma unroll
            for (int j = 0; j < 4; j++) s[i][j] = 0.0f;

#pragma unroll 8
        for (int c = 0; c < 64; c++) {
            float4 qv = *reinterpret_cast<const float4*>(QsT + c * LDS_ + 4 * ty);
            float4 kv = *reinterpret_cast<const float4*>(KsT + c * LDS_ + 4 * tx);
            s[0][0] += qv.x * kv.x; s[0][1] += qv.x * kv.y; s[0][2] += qv.x * kv.z; s[0][3] += qv.x * kv.w;
            s[1][0] += qv.y * kv.x; s[1][1] += qv.y * kv.y; s[1][2] += qv.y * kv.z; s[1][3] += qv.y * kv.w;
            s[2][0] += qv.z * kv.x; s[2][1] += qv.z * kv.y; s[2][2] += qv.z * kv.z; s[2][3] += qv.z * kv.w;
            s[3][0] += qv.w * kv.x; s[3][1] += qv.w * kv.y; s[3][2] += qv.w * kv.z; s[3][3] += qv.w * kv.w;
        }

        // Online softmax per row (reduce across the 16 tx lanes = one 16-lane half-warp)
#pragma unroll
        for (int i = 0; i < 4; i++) {
            float mi = fmaxf(fmaxf(s[i][0], s[i][1]), fmaxf(s[i][2], s[i][3]));
#pragma unroll
            for (int off = 8; off >= 1; off >>= 1)
                mi = fmaxf(mi, __shfl_xor_sync(0xffffffffu, mi, off));
            float mnew  = fmaxf(mrow[i], mi);
            float alpha = __expf(mrow[i] - mnew);
            mrow[i] = mnew;
            float p0 = __expf(s[i][0] - mnew);
            float p1 = __expf(s[i][1] - mnew);
            float p2 = __expf(s[i][2] - mnew);
            float p3 = __expf(s[i][3] - mnew);
            float li = (p0 + p1) + (p2 + p3);
#pragma unroll
            for (int off = 8; off >= 1; off >>= 1)
                li += __shfl_xor_sync(0xffffffffu, li, off);
            lrow[i] = lrow[i] * alpha + li;
            o[i][0] *= alpha; o[i][1] *= alpha; o[i][2] *= alpha; o[i][3] *= alpha;
            *reinterpret_cast<float4*>(Ps + (4 * ty + i) * LDS_ + 4 * tx) = make_float4(p0, p1, p2, p3);
        }
        __syncthreads();

        // GEMM2: O += P * V
#pragma unroll 8
        for (int k = 0; k < 64; k++) {
            float4 vv = *reinterpret_cast<const float4*>(Vs + k * LDS_ + 4 * tx);
#pragma unroll
            for (int i = 0; i < 4; i++) {
                float pr = Ps[(4 * ty + i) * LDS_ + k];
                o[i][0] += pr * vv.x; o[i][1] += pr * vv.y;
                o[i][2] += pr * vv.z; o[i][3] += pr * vv.w;
            }
        }
    }
    __syncthreads();

    // Load per-query frames (forward lframes) into smem (reuse KsT space)
    float* Fr = KsT;  // 64 rows x 16
#pragma unroll
    for (int rep = 0; rep < 4; rep++) {
        int idx = rep * 256 + t;    // 0..1023
        int r = idx >> 4;
        int e = idx & 15;
        Fr[r * 16 + e] = lframes[((long)(b * N_ + q0 + r)) * 16 + e];
    }
    __syncthreads();

    // Epilogue: normalize + fused output frame transform + store
#pragma unroll
    for (int i = 0; i < 4; i++) {
        int r = 4 * ty + i;
        float invl = 1.0f / lrow[i];
        float x0 = o[i][0] * invl, x1 = o[i][1] * invl, x2 = o[i][2] * invl, x3 = o[i][3] * invl;
        float y0, y1, y2, y3;
        if (tx < 4) {               // scalar channels pass through
            y0 = x0; y1 = x1; y2 = x2; y3 = x3;
        } else {                    // exactly one 4-vector: rotate by lframes[b, q0+r]
            const float* M = Fr + r * 16;
            y0 = M[0]  * x0 + M[1]  * x1 + M[2]  * x2 + M[3]  * x3;
            y1 = M[4]  * x0 + M[5]  * x1 + M[6]  * x2 + M[7]  * x3;
            y2 = M[8]  * x0 + M[9]  * x1 + M[10] * x2 + M[11] * x3;
            y3 = M[12] * x0 + M[13] * x1 + M[14] * x2 + M[15] * x3;
        }
        *reinterpret_cast<float4*>(out + base + (long)(q0 + r) * C_ + 4 * tx) =
            make_float4(y0, y1, y2, y3);
    }
}

// ---------------------------------------------------------------------------
extern "C" void kernel_launch(void* const* d_in, const int* in_sizes, int n_in,
                              void* d_out, int out_size) {
    // Identify lframes by element count (262144); q/k/v keep dict order.
    const float* big[3] = {nullptr, nullptr, nullptr};
    const float* lf = nullptr;
    int nb = 0;
    for (int i = 0; i < n_in; i++) {
        if (in_sizes[i] == FR_ELEMS && lf == nullptr) lf = (const float*)d_in[i];
        else if (nb < 3) big[nb++] = (const float*)d_in[i];
    }
    const float* q = big[0];
    const float* k = big[1];
    const float* v = big[2];
    float* out = (float*)d_out;

    frames_kernel<<<(B_ * N_ + 255) / 256, 256>>>(lf);
    transform_kernel<<<(B_ * H_ * N_ + 255) / 256, 256>>>(q, k, v);

    const int smem_bytes = 4 * TILE_FLOATS * (int)sizeof(float);  // 69632
    cudaFuncSetAttribute(attn_kernel, cudaFuncAttributeMaxDynamicSharedMemorySize, smem_bytes);
    attn_kernel<<<dim3(8, 256), 256, smem_bytes>>>(lf, out);
}

// round 3
// speedup vs baseline: 2.6950x; 2.6950x over previous
#include <cuda_runtime.h>
#include <cuda_bf16.h>
#include <cstdint>

static constexpr int B_ = 32;
static constexpr int H_ = 8;
static constexpr int N_ = 512;
static constexpr int C_ = 64;
static constexpr long QKV_ELEMS = (long)B_ * H_ * N_ * C_;   // 8,388,608
static constexpr int  FR_ELEMS  = B_ * N_ * 16;              // 262,144

// ---- scratch (static device arrays are allowed) ----
__device__ float g_inv[FR_ELEMS];
__device__ float g_linv[FR_ELEMS];
__device__ __align__(16) __nv_bfloat16 g_qh[QKV_ELEMS];
__device__ __align__(16) __nv_bfloat16 g_ql[QKV_ELEMS];
__device__ __align__(16) __nv_bfloat16 g_kh[QKV_ELEMS];
__device__ __align__(16) __nv_bfloat16 g_kl[QKV_ELEMS];
__device__ __align__(16) __nv_bfloat16 g_vh[QKV_ELEMS];
__device__ __align__(16) __nv_bfloat16 g_vl[QKV_ELEMS];

// ============================ helpers ============================
__device__ __forceinline__ uint32_t smem_u32(const void* p) {
    uint32_t a;
    asm("{ .reg .u64 t; cvta.to.shared.u64 t, %1; cvt.u32.u64 %0, t; }" : "=r"(a) : "l"(p));
    return a;
}
__device__ __forceinline__ uint32_t swz(uint32_t byte) {
    return byte ^ ((byte >> 3) & 0x70);
}
__device__ __forceinline__ void ldsm4(uint32_t* r, uint32_t addr) {
    asm volatile("ldmatrix.sync.aligned.m8n8.x4.shared.b16 {%0,%1,%2,%3}, [%4];"
                 : "=r"(r[0]), "=r"(r[1]), "=r"(r[2]), "=r"(r[3]) : "r"(addr));
}
__device__ __forceinline__ void ldsm4t(uint32_t* r, uint32_t addr) {
    asm volatile("ldmatrix.sync.aligned.m8n8.x4.trans.shared.b16 {%0,%1,%2,%3}, [%4];"
                 : "=r"(r[0]), "=r"(r[1]), "=r"(r[2]), "=r"(r[3]) : "r"(addr));
}
__device__ __forceinline__ void mma16816(float* d, const uint32_t* a, const uint32_t* b) {
    asm volatile("mma.sync.aligned.m16n8k16.row.col.f32.bf16.bf16.f32 "
                 "{%0,%1,%2,%3}, {%4,%5,%6,%7}, {%8,%9}, {%0,%1,%2,%3};"
                 : "+f"(d[0]), "+f"(d[1]), "+f"(d[2]), "+f"(d[3])
                 : "r"(a[0]), "r"(a[1]), "r"(a[2]), "r"(a[3]), "r"(b[0]), "r"(b[1]));
}
__device__ __forceinline__ uint32_t pack_bf16x2(float x, float y) {
    __nv_bfloat16 a = __float2bfloat16_rn(x);
    __nv_bfloat16 b = __float2bfloat16_rn(y);
    return (uint32_t)__bfloat16_as_ushort(a) | ((uint32_t)__bfloat16_as_ushort(b) << 16);
}

// ============================ kernel 1: frames ============================
__global__ void frames_kernel(const float* __restrict__ lframes) {
    int idx = blockIdx.x * blockDim.x + threadIdx.x;
    if (idx >= B_ * N_) return;
    float m[16];
#pragma unroll
    for (int i = 0; i < 16; i++) m[i] = lframes[(long)idx * 16 + i];
    float inv[16];
    inv[0]  =  m[5]*m[10]*m[15] - m[5]*m[11]*m[14] - m[9]*m[6]*m[15] + m[9]*m[7]*m[14] + m[13]*m[6]*m[11] - m[13]*m[7]*m[10];
    inv[4]  = -m[4]*m[10]*m[15] + m[4]*m[11]*m[14] + m[8]*m[6]*m[15] - m[8]*m[7]*m[14] - m[12]*m[6]*m[11] + m[12]*m[7]*m[10];
    inv[8]  =  m[4]*m[9]*m[15]  - m[4]*m[11]*m[13] - m[8]*m[5]*m[15] + m[8]*m[7]*m[13] + m[12]*m[5]*m[11] - m[12]*m[7]*m[9];
    inv[12] = -m[4]*m[9]*m[14]  + m[4]*m[10]*m[13] + m[8]*m[5]*m[14] - m[8]*m[6]*m[13] - m[12]*m[5]*m[10] + m[12]*m[6]*m[9];
    inv[1]  = -m[1]*m[10]*m[15] + m[1]*m[11]*m[14] + m[9]*m[2]*m[15] - m[9]*m[3]*m[14] - m[13]*m[2]*m[11] + m[13]*m[3]*m[10];
    inv[5]  =  m[0]*m[10]*m[15] - m[0]*m[11]*m[14] - m[8]*m[2]*m[15] + m[8]*m[3]*m[14] + m[12]*m[2]*m[11] - m[12]*m[3]*m[10];
    inv[9]  = -m[0]*m[9]*m[15]  + m[0]*m[11]*m[13] + m[8]*m[1]*m[15] - m[8]*m[3]*m[13] - m[12]*m[1]*m[11] + m[12]*m[3]*m[9];
    inv[13] =  m[0]*m[9]*m[14]  - m[0]*m[10]*m[13] - m[8]*m[1]*m[14] + m[8]*m[2]*m[13] + m[12]*m[1]*m[10] - m[12]*m[2]*m[9];
    inv[2]  =  m[1]*m[6]*m[15]  - m[1]*m[7]*m[14]  - m[5]*m[2]*m[15] + m[5]*m[3]*m[14] + m[13]*m[2]*m[7]  - m[13]*m[3]*m[6];
    inv[6]  = -m[0]*m[6]*m[15]  + m[0]*m[7]*m[14]  + m[4]*m[2]*m[15] - m[4]*m[3]*m[14] - m[12]*m[2]*m[7]  + m[12]*m[3]*m[6];
    inv[10] =  m[0]*m[5]*m[15]  - m[0]*m[7]*m[13]  - m[4]*m[1]*m[15] + m[4]*m[3]*m[13] + m[12]*m[1]*m[7]  - m[12]*m[3]*m[5];
    inv[14] = -m[0]*m[5]*m[14]  + m[0]*m[6]*m[13]  + m[4]*m[1]*m[14] - m[4]*m[2]*m[13] - m[12]*m[1]*m[6]  + m[12]*m[2]*m[5];
    inv[3]  = -m[1]*m[6]*m[11]  + m[1]*m[7]*m[10]  + m[5]*m[2]*m[11] - m[5]*m[3]*m[10] - m[9]*m[2]*m[7]   + m[9]*m[3]*m[6];
    inv[7]  =  m[0]*m[6]*m[11]  - m[0]*m[7]*m[10]  - m[4]*m[2]*m[11] + m[4]*m[3]*m[10] + m[8]*m[2]*m[7]   - m[8]*m[3]*m[6];
    inv[11] = -m[0]*m[5]*m[11]  + m[0]*m[7]*m[9]   + m[4]*m[1]*m[11] - m[4]*m[3]*m[9]  - m[8]*m[1]*m[7]   + m[8]*m[3]*m[5];
    inv[15] =  m[0]*m[5]*m[10]  - m[0]*m[6]*m[9]   - m[4]*m[1]*m[10] + m[4]*m[2]*m[9]  + m[8]*m[1]*m[6]   - m[8]*m[2]*m[5];
    float det = m[0]*inv[0] + m[1]*inv[4] + m[2]*inv[8] + m[3]*inv[12];
    float d = 1.0f / det;
#pragma unroll
    for (int i = 0; i < 16; i++) {
        float val = inv[i] * d;
        g_inv[(long)idx * 16 + i] = val;
        int r = i >> 2, c = i & 3;
        float sgn = ((r == 0) == (c == 0)) ? 1.0f : -1.0f;
        g_linv[(long)idx * 16 + i] = sgn * val;
    }
}

// ============================ kernel 2: transform + hi/lo split ============================
__device__ __forceinline__ void rot4(float* x, const float* M) {
    float y0 = M[0]*x[0] + M[1]*x[1] + M[2]*x[2] + M[3]*x[3];
    float y1 = M[4]*x[0] + M[5]*x[1] + M[6]*x[2] + M[7]*x[3];
    float y2 = M[8]*x[0] + M[9]*x[1] + M[10]*x[2] + M[11]*x[3];
    float y3 = M[12]*x[0] + M[13]*x[1] + M[14]*x[2] + M[15]*x[3];
    x[0] = y0; x[1] = y1; x[2] = y2; x[3] = y3;
}
__device__ __forceinline__ void store_hilo(__nv_bfloat16* gh, __nv_bfloat16* gl,
                                           long base, const float* x) {
    uint32_t hw[8], lw[8];
#pragma unroll
    for (int j = 0; j < 8; j++) {
        __nv_bfloat16 h0 = __float2bfloat16_rn(x[2*j]);
        __nv_bfloat16 h1 = __float2bfloat16_rn(x[2*j+1]);
        float l0 = x[2*j]   - __bfloat162float(h0);
        float l1 = x[2*j+1] - __bfloat162float(h1);
        hw[j] = (uint32_t)__bfloat16_as_ushort(h0) | ((uint32_t)__bfloat16_as_ushort(h1) << 16);
        lw[j] = pack_bf16x2(l0, l1);
    }
    uint4* ph = reinterpret_cast<uint4*>(gh + base);
    uint4* pl = reinterpret_cast<uint4*>(gl + base);
    ph[0] = make_uint4(hw[0], hw[1], hw[2], hw[3]);
    ph[1] = make_uint4(hw[4], hw[5], hw[6], hw[7]);
    pl[0] = make_uint4(lw[0], lw[1], lw[2], lw[3]);
    pl[1] = make_uint4(lw[4], lw[5], lw[6], lw[7]);
}

__global__ void transform_kernel(const float* __restrict__ q,
                                 const float* __restrict__ k,
                                 const float* __restrict__ v) {
    int t = blockIdx.x * blockDim.x + threadIdx.x;
    if (t >= B_ * H_ * N_ * 4) return;
    int qd  = t & 3;
    int idx = t >> 2;
    int n = idx % N_;
    int b = idx / (H_ * N_);
    long base = (long)idx * C_ + qd * 16;

    float xq[16], xk[16], xv[16];
#pragma unroll
    for (int i = 0; i < 4; i++) {
        float4 a;
        a = reinterpret_cast<const float4*>(q + base)[i];
        xq[4*i] = a.x; xq[4*i+1] = a.y; xq[4*i+2] = a.z; xq[4*i+3] = a.w;
        a = reinterpret_cast<const float4*>(k + base)[i];
        xk[4*i] = a.x; xk[4*i+1] = a.y; xk[4*i+2] = a.z; xk[4*i+3] = a.w;
        a = reinterpret_cast<const float4*>(v + base)[i];
        xv[4*i] = a.x; xv[4*i+1] = a.y; xv[4*i+2] = a.z; xv[4*i+3] = a.w;
    }
    if (qd > 0) {
        long fb = (long)(b * N_ + n) * 16;
        float mi[16], ml[16];
#pragma unroll
        for (int i = 0; i < 16; i++) { mi[i] = g_inv[fb + i]; ml[i] = g_linv[fb + i]; }
#pragma unroll
        for (int vv = 0; vv < 4; vv++) {
            rot4(xq + 4*vv, mi);
            rot4(xk + 4*vv, ml);
            rot4(xv + 4*vv, mi);
        }
    }
#pragma unroll
    for (int i = 0; i < 16; i++) xq[i] *= 0.125f;   // fold 1/sqrt(C)

    store_hilo(g_qh, g_ql, base, xq);
    store_hilo(g_kh, g_kl, base, xk);
    store_hilo(g_vh, g_vl, base, xv);
}

// ============================ kernel 3: mma.sync flash attention ============================
// smem layout (bytes): all tiles row-major, 128B rows, SW128 swizzle
static constexpr int SQH = 0;          //  64 x 64 bf16  (8KB)
static constexpr int SQL = 8192;
static constexpr int SKH = 16384;      // 128 x 64 bf16 (16KB)
static constexpr int SKL = 32768;
static constexpr int SVH = 49152;
static constexpr int SVL = 65536;
static constexpr int SMEM_TOTAL = 81920;
static constexpr int OF_PITCH = 72;    // floats; 288B rows (16B-aligned)

__device__ __forceinline__ void copy64(const __nv_bfloat16* __restrict__ g, char* s, int tid) {
    const uint4* g4 = reinterpret_cast<const uint4*>(g);
#pragma unroll
    for (int i = 0; i < 4; i++) {
        int idx = i * 128 + tid;
        uint32_t byte = (uint32_t)((idx >> 3) * 128 + (idx & 7) * 16);
        *reinterpret_cast<uint4*>(s + swz(byte)) = g4[idx];
    }
}
__device__ __forceinline__ void copy128(const __nv_bfloat16* __restrict__ g, char* s, int tid) {
    const uint4* g4 = reinterpret_cast<const uint4*>(g);
#pragma unroll
    for (int i = 0; i < 8; i++) {
        int idx = i * 128 + tid;
        uint32_t byte = (uint32_t)((idx >> 3) * 128 + (idx & 7) * 16);
        *reinterpret_cast<uint4*>(s + swz(byte)) = g4[idx];
    }
}

__global__ void __launch_bounds__(128) attn_kernel(const float* __restrict__ lframes,
                                                   float* __restrict__ out) {
    extern __shared__ char smem[];
    const uint32_t sb = smem_u32(smem);
    const int tid  = threadIdx.x;
    const int warp = tid >> 5;
    const int lane = tid & 31;
    const int qt = blockIdx.x;          // 0..7
    const int bh = blockIdx.y;          // 0..255
    const int b  = bh >> 3;
    const long base = (long)bh * (N_ * C_);
    const int q0 = qt * 64;

    copy64(g_qh + base + (long)q0 * C_, smem + SQH, tid);
    copy64(g_ql + base + (long)q0 * C_, smem + SQL, tid);
    __syncthreads();

    // preload Q fragments (4 k-chunks x 4 regs, hi & lo)
    uint32_t qh[4][4], ql[4][4];
    {
        uint32_t row = (uint32_t)(warp * 16 + (lane & 15));
        uint32_t ch  = (uint32_t)((lane >> 4) * 16);
#pragma unroll
        for (int kc = 0; kc < 4; kc++) {
            uint32_t off = swz(row * 128 + kc * 32 + ch);
            ldsm4(qh[kc], sb + SQH + off);
            ldsm4(ql[kc], sb + SQL + off);
        }
    }

    float ot[8][4];
#pragma unroll
    for (int j = 0; j < 8; j++)
#pragma unroll
        for (int e = 0; e < 4; e++) ot[j][e] = 0.0f;
    float m0 = -1e30f, m1 = -1e30f, l0 = 0.0f, l1 = 0.0f;

    // B-fragment lane addressing (precomputed pieces)
    const uint32_t k_nb  = (uint32_t)(lane >> 4);        // n-block (0/1)
    const uint32_t k_kh  = (uint32_t)((lane >> 3) & 1);  // k-half (0/1)
    const uint32_t k_l7  = (uint32_t)(lane & 7);

    for (int kc4 = 0; kc4 < 4; kc4++) {
        __syncthreads();
        const long kb = base + (long)kc4 * 128 * C_;
        copy128(g_kh + kb, smem + SKH, tid);
        copy128(g_kl + kb, smem + SKL, tid);
        copy128(g_vh + kb, smem + SVH, tid);
        copy128(g_vl + kb, smem + SVL, tid);
        __syncthreads();

        // ---- GEMM1: S[16 tiles] = Qh*Kh^T + Qh*Kl^T + Ql*Kh^T ----
        float st[16][4];
#pragma unroll
        for (int j = 0; j < 16; j++)
#pragma unroll
            for (int e = 0; e < 4; e++) st[j][e] = 0.0f;

#pragma unroll
        for (int kcc = 0; kcc < 4; kcc++) {
#pragma unroll
            for (int np = 0; np < 8; np++) {
                uint32_t key = (uint32_t)(np * 16) + k_nb * 8 + k_l7;
                uint32_t off = swz(key * 128 + (uint32_t)(kcc * 32) + k_kh * 16);
                uint32_t bh4[4], bl4[4];
                ldsm4(bh4, sb + SKH + off);
                ldsm4(bl4, sb + SKL + off);
                mma16816(st[2*np],   qh[kcc], bh4);
                mma16816(st[2*np+1], qh[kcc], bh4 + 2);
                mma16816(st[2*np],   qh[kcc], bl4);
                mma16816(st[2*np+1], qh[kcc], bl4 + 2);
                mma16816(st[2*np],   ql[kcc], bh4);
                mma16816(st[2*np+1], ql[kcc], bh4 + 2);
            }
        }

        // ---- online softmax (rows t/4 and t/4+8 of this warp's 16) ----
        float mx0 = st[0][0], mx1 = st[0][2];
#pragma unroll
        for (int j = 0; j < 16; j++) {
            mx0 = fmaxf(mx0, fmaxf(st[j][0], st[j][1]));
            mx1 = fmaxf(mx1, fmaxf(st[j][2], st[j][3]));
        }
#pragma unroll
        for (int o = 1; o <= 2; o <<= 1) {
            mx0 = fmaxf(mx0, __shfl_xor_sync(0xffffffffu, mx0, o));
            mx1 = fmaxf(mx1, __shfl_xor_sync(0xffffffffu, mx1, o));
        }
        float mn0 = fmaxf(m0, mx0), mn1 = fmaxf(m1, mx1);
        float a0 = __expf(m0 - mn0), a1 = __expf(m1 - mn1);
        m0 = mn0; m1 = mn1;

        uint32_t pH[16][2], pL[16][2];
        float s0 = 0.0f, s1 = 0.0f;
#pragma unroll
        for (int j = 0; j < 16; j++) {
            float p00 = __expf(st[j][0] - m0);
            float p01 = __expf(st[j][1] - m0);
            float p10 = __expf(st[j][2] - m1);
            float p11 = __expf(st[j][3] - m1);
            s0 += p00 + p01; s1 += p10 + p11;
            __nv_bfloat16 h00 = __float2bfloat16_rn(p00);
            __nv_bfloat16 h01 = __float2bfloat16_rn(p01);
            __nv_bfloat16 h10 = __float2bfloat16_rn(p10);
            __nv_bfloat16 h11 = __float2bfloat16_rn(p11);
            pH[j][0] = (uint32_t)__bfloat16_as_ushort(h00) | ((uint32_t)__bfloat16_as_ushort(h01) << 16);
            pH[j][1] = (uint32_t)__bfloat16_as_ushort(h10) | ((uint32_t)__bfloat16_as_ushort(h11) << 16);
            pL[j][0] = pack_bf16x2(p00 - __bfloat162float(h00), p01 - __bfloat162float(h01));
            pL[j][1] = pack_bf16x2(p10 - __bfloat162float(h10), p11 - __bfloat162float(h11));
        }
#pragma unroll
        for (int o = 1; o <= 2; o <<= 1) {
            s0 += __shfl_xor_sync(0xffffffffu, s0, o);
            s1 += __shfl_xor_sync(0xffffffffu, s1, o);
        }
        l0 = l0 * a0 + s0;
        l1 = l1 * a1 + s1;
#pragma unroll
        for (int j = 0; j < 8; j++) {
            ot[j][0] *= a0; ot[j][1] *= a0;
            ot[j][2] *= a1; ot[j][3] *= a1;
        }

        // ---- GEMM2: O += Ph*Vh + Ph*Vl + Pl*Vh ----
#pragma unroll
        for (int ks = 0; ks < 8; ks++) {
            uint32_t aH[4] = {pH[2*ks][0], pH[2*ks][1], pH[2*ks+1][0], pH[2*ks+1][1]};
            uint32_t aL[4] = {pL[2*ks][0], pL[2*ks][1], pL[2*ks+1][0], pL[2*ks+1][1]};
            uint32_t vrow = (uint32_t)(ks * 16) + k_kh * 8 + k_l7;
#pragma unroll
            for (int np = 0; np < 4; np++) {
                uint32_t off = swz(vrow * 128 + (uint32_t)(np * 32) + k_nb * 16);
                uint32_t bh4[4], bl4[4];
                ldsm4t(bh4, sb + SVH + off);
                ldsm4t(bl4, sb + SVL + off);
                mma16816(ot[2*np],   aH, bh4);
                mma16816(ot[2*np+1], aH, bh4 + 2);
                mma16816(ot[2*np],   aH, bl4);
                mma16816(ot[2*np+1], aH, bl4 + 2);
                mma16816(ot[2*np],   aL, bh4);
                mma16816(ot[2*np+1], aL, bh4 + 2);
            }
        }
    }

    // ---- epilogue: normalize, roundtrip via smem, fused frame transform ----
    __syncthreads();
    float* Of = reinterpret_cast<float*>(smem + SKH);   // [64][OF_PITCH]
    {
        float inv0 = 1.0f / l0, inv1 = 1.0f / l1;
        int r0 = warp * 16 + (lane >> 2);
        int r1 = r0 + 8;
        int cb = 2 * (lane & 3);
#pragma unroll
        for (int j = 0; j < 8; j++) {
            int col = j * 8 + cb;
            *reinterpret_cast<float2*>(Of + r0 * OF_PITCH + col) =
                make_float2(ot[j][0] * inv0, ot[j][1] * inv0);
            *reinterpret_cast<float2*>(Of + r1 * OF_PITCH + col) =
                make_float2(ot[j][2] * inv1, ot[j][3] * inv1);
        }
    }
    __syncthreads();

#pragma unroll
    for (int it = 0; it < 8; it++) {
        int task = it * 128 + tid;      // 0..1023
        int rr = task >> 4;
        int g  = task & 15;
        const float* src = Of + rr * OF_PITCH + g * 4;
        float x0 = src[0], x1 = src[1], x2 = src[2], x3 = src[3];
        float y0, y1, y2, y3;
        if (g < 4) {
            y0 = x0; y1 = x1; y2 = x2; y3 = x3;
        } else {
            const float* M = lframes + (long)(b * N_ + q0 + rr) * 16;
            y0 = M[0]  * x0 + M[1]  * x1 + M[2]  * x2 + M[3]  * x3;
            y1 = M[4]  * x0 + M[5]  * x1 + M[6]  * x2 + M[7]  * x3;
            y2 = M[8]  * x0 + M[9]  * x1 + M[10] * x2 + M[11] * x3;
            y3 = M[12] * x0 + M[13] * x1 + M[14] * x2 + M[15] * x3;
        }
        *reinterpret_cast<float4*>(out + base + (long)(q0 + rr) * C_ + g * 4) =
            make_float4(y0, y1, y2, y3);
    }
}

// ---------------------------------------------------------------------------
extern "C" void kernel_launch(void* const* d_in, const int* in_sizes, int n_in,
                              void* d_out, int out_size) {
    const float* big[3] = {nullptr, nullptr, nullptr};
    const float* lf = nullptr;
    int nb = 0;
    for (int i = 0; i < n_in; i++) {
        if (in_sizes[i] == FR_ELEMS && lf == nullptr) lf = (const float*)d_in[i];
        else if (nb < 3) big[nb++] = (const float*)d_in[i];
    }
    const float* q = big[0];
    const float* k = big[1];
    const float* v = big[2];
    float* out = (float*)d_out;

    frames_kernel<<<(B_ * N_ + 255) / 256, 256>>>(lf);
    transform_kernel<<<(B_ * H_ * N_ * 4 + 255) / 256, 256>>>(q, k, v);

    cudaFuncSetAttribute(attn_kernel, cudaFuncAttributeMaxDynamicSharedMemorySize, SMEM_TOTAL);
    attn_kernel<<<dim3(8, 256), 128, SMEM_TOTAL>>>(lf, out);
}

// round 4
// speedup vs baseline: 3.0428x; 1.1291x over previous
#include <cuda_runtime.h>
#include <cuda_bf16.h>
#include <cstdint>

static constexpr int B_ = 32;
static constexpr int H_ = 8;
static constexpr int N_ = 512;
static constexpr int C_ = 64;
static constexpr long QKV_ELEMS = (long)B_ * H_ * N_ * C_;   // 8,388,608
static constexpr int  FR_ELEMS  = B_ * N_ * 16;              // 262,144

// ---- scratch (static device arrays are allowed) ----
__device__ float g_inv[FR_ELEMS];
__device__ float g_linv[FR_ELEMS];
__device__ __align__(16) __nv_bfloat16 g_qh[QKV_ELEMS];
__device__ __align__(16) __nv_bfloat16 g_ql[QKV_ELEMS];
__device__ __align__(16) __nv_bfloat16 g_kh[QKV_ELEMS];
__device__ __align__(16) __nv_bfloat16 g_kl[QKV_ELEMS];
__device__ __align__(16) __nv_bfloat16 g_vh[QKV_ELEMS];
__device__ __align__(16) __nv_bfloat16 g_vl[QKV_ELEMS];

// ============================ helpers ============================
__device__ __forceinline__ uint32_t smem_u32(const void* p) {
    uint32_t a;
    asm("{ .reg .u64 t; cvta.to.shared.u64 t, %1; cvt.u32.u64 %0, t; }" : "=r"(a) : "l"(p));
    return a;
}
__device__ __forceinline__ uint32_t swz(uint32_t byte) {
    return byte ^ ((byte >> 3) & 0x70);
}
__device__ __forceinline__ void ldsm4(uint32_t* r, uint32_t addr) {
    asm volatile("ldmatrix.sync.aligned.m8n8.x4.shared.b16 {%0,%1,%2,%3}, [%4];"
                 : "=r"(r[0]), "=r"(r[1]), "=r"(r[2]), "=r"(r[3]) : "r"(addr));
}
__device__ __forceinline__ void ldsm4t(uint32_t* r, uint32_t addr) {
    asm volatile("ldmatrix.sync.aligned.m8n8.x4.trans.shared.b16 {%0,%1,%2,%3}, [%4];"
                 : "=r"(r[0]), "=r"(r[1]), "=r"(r[2]), "=r"(r[3]) : "r"(addr));
}
__device__ __forceinline__ void mma16816(float* d, const uint32_t* a, const uint32_t* b) {
    asm volatile("mma.sync.aligned.m16n8k16.row.col.f32.bf16.bf16.f32 "
                 "{%0,%1,%2,%3}, {%4,%5,%6,%7}, {%8,%9}, {%0,%1,%2,%3};"
                 : "+f"(d[0]), "+f"(d[1]), "+f"(d[2]), "+f"(d[3])
                 : "r"(a[0]), "r"(a[1]), "r"(a[2]), "r"(a[3]), "r"(b[0]), "r"(b[1]));
}
__device__ __forceinline__ uint32_t pack_bf16x2(float x, float y) {
    __nv_bfloat16 a = __float2bfloat16_rn(x);
    __nv_bfloat16 b = __float2bfloat16_rn(y);
    return (uint32_t)__bfloat16_as_ushort(a) | ((uint32_t)__bfloat16_as_ushort(b) << 16);
}
__device__ __forceinline__ float ex2f(float x) {
    float r;
    asm("ex2.approx.f32 %0, %1;" : "=f"(r) : "f"(x));
    return r;
}
#define CP_ASYNC16(dst, src) \
    asm volatile("cp.async.cg.shared.global [%0], [%1], 16;" :: "r"(dst), "l"(src) : "memory")
#define CP_COMMIT() asm volatile("cp.async.commit_group;" ::: "memory")
#define CP_WAIT(n)  asm volatile("cp.async.wait_group %0;" :: "n"(n) : "memory")

// ============================ kernel 1: frames ============================
__global__ void frames_kernel(const float* __restrict__ lframes) {
    int idx = blockIdx.x * blockDim.x + threadIdx.x;
    if (idx >= B_ * N_) return;
    float m[16];
#pragma unroll
    for (int i = 0; i < 16; i++) m[i] = lframes[(long)idx * 16 + i];
    float inv[16];
    inv[0]  =  m[5]*m[10]*m[15] - m[5]*m[11]*m[14] - m[9]*m[6]*m[15] + m[9]*m[7]*m[14] + m[13]*m[6]*m[11] - m[13]*m[7]*m[10];
    inv[4]  = -m[4]*m[10]*m[15] + m[4]*m[11]*m[14] + m[8]*m[6]*m[15] - m[8]*m[7]*m[14] - m[12]*m[6]*m[11] + m[12]*m[7]*m[10];
    inv[8]  =  m[4]*m[9]*m[15]  - m[4]*m[11]*m[13] - m[8]*m[5]*m[15] + m[8]*m[7]*m[13] + m[12]*m[5]*m[11] - m[12]*m[7]*m[9];
    inv[12] = -m[4]*m[9]*m[14]  + m[4]*m[10]*m[13] + m[8]*m[5]*m[14] - m[8]*m[6]*m[13] - m[12]*m[5]*m[10] + m[12]*m[6]*m[9];
    inv[1]  = -m[1]*m[10]*m[15] + m[1]*m[11]*m[14] + m[9]*m[2]*m[15] - m[9]*m[3]*m[14] - m[13]*m[2]*m[11] + m[13]*m[3]*m[10];
    inv[5]  =  m[0]*m[10]*m[15] - m[0]*m[11]*m[14] - m[8]*m[2]*m[15] + m[8]*m[3]*m[14] + m[12]*m[2]*m[11] - m[12]*m[3]*m[10];
    inv[9]  = -m[0]*m[9]*m[15]  + m[0]*m[11]*m[13] + m[8]*m[1]*m[15] - m[8]*m[3]*m[13] - m[12]*m[1]*m[11] + m[12]*m[3]*m[9];
    inv[13] =  m[0]*m[9]*m[14]  - m[0]*m[10]*m[13] - m[8]*m[1]*m[14] + m[8]*m[2]*m[13] + m[12]*m[1]*m[10] - m[12]*m[2]*m[9];
    inv[2]  =  m[1]*m[6]*m[15]  - m[1]*m[7]*m[14]  - m[5]*m[2]*m[15] + m[5]*m[3]*m[14] + m[13]*m[2]*m[7]  - m[13]*m[3]*m[6];
    inv[6]  = -m[0]*m[6]*m[15]  + m[0]*m[7]*m[14]  + m[4]*m[2]*m[15] - m[4]*m[3]*m[14] - m[12]*m[2]*m[7]  + m[12]*m[3]*m[6];
    inv[10] =  m[0]*m[5]*m[15]  - m[0]*m[7]*m[13]  - m[4]*m[1]*m[15] + m[4]*m[3]*m[13] + m[12]*m[1]*m[7]  - m[12]*m[3]*m[5];
    inv[14] = -m[0]*m[5]*m[14]  + m[0]*m[6]*m[13]  + m[4]*m[1]*m[14] - m[4]*m[2]*m[13] - m[12]*m[1]*m[6]  + m[12]*m[2]*m[5];
    inv[3]  = -m[1]*m[6]*m[11]  + m[1]*m[7]*m[10]  + m[5]*m[2]*m[11] - m[5]*m[3]*m[10] - m[9]*m[2]*m[7]   + m[9]*m[3]*m[6];
    inv[7]  =  m[0]*m[6]*m[11]  - m[0]*m[7]*m[10]  - m[4]*m[2]*m[11] + m[4]*m[3]*m[10] + m[8]*m[2]*m[7]   - m[8]*m[3]*m[6];
    inv[11] = -m[0]*m[5]*m[11]  + m[0]*m[7]*m[9]   + m[4]*m[1]*m[11] - m[4]*m[3]*m[9]  - m[8]*m[1]*m[7]   + m[8]*m[3]*m[5];
    inv[15] =  m[0]*m[5]*m[10]  - m[0]*m[6]*m[9]   - m[4]*m[1]*m[10] + m[4]*m[2]*m[9]  + m[8]*m[1]*m[6]   - m[8]*m[2]*m[5];
    float det = m[0]*inv[0] + m[1]*inv[4] + m[2]*inv[8] + m[3]*inv[12];
    float d = 1.0f / det;
#pragma unroll
    for (int i = 0; i < 16; i++) {
        float val = inv[i] * d;
        g_inv[(long)idx * 16 + i] = val;
        int r = i >> 2, c = i & 3;
        float sgn = ((r == 0) == (c == 0)) ? 1.0f : -1.0f;
        g_linv[(long)idx * 16 + i] = sgn * val;
    }
}

// ============================ kernel 2: transform + hi/lo split ============================
__device__ __forceinline__ void rot4(float* x, const float* M) {
    float y0 = M[0]*x[0] + M[1]*x[1] + M[2]*x[2] + M[3]*x[3];
    float y1 = M[4]*x[0] + M[5]*x[1] + M[6]*x[2] + M[7]*x[3];
    float y2 = M[8]*x[0] + M[9]*x[1] + M[10]*x[2] + M[11]*x[3];
    float y3 = M[12]*x[0] + M[13]*x[1] + M[14]*x[2] + M[15]*x[3];
    x[0] = y0; x[1] = y1; x[2] = y2; x[3] = y3;
}
__device__ __forceinline__ void store_hilo(__nv_bfloat16* gh, __nv_bfloat16* gl,
                                           long base, const float* x) {
    uint32_t hw[8], lw[8];
#pragma unroll
    for (int j = 0; j < 8; j++) {
        __nv_bfloat16 h0 = __float2bfloat16_rn(x[2*j]);
        __nv_bfloat16 h1 = __float2bfloat16_rn(x[2*j+1]);
        float l0 = x[2*j]   - __bfloat162float(h0);
        float l1 = x[2*j+1] - __bfloat162float(h1);
        hw[j] = (uint32_t)__bfloat16_as_ushort(h0) | ((uint32_t)__bfloat16_as_ushort(h1) << 16);
        lw[j] = pack_bf16x2(l0, l1);
    }
    uint4* ph = reinterpret_cast<uint4*>(gh + base);
    uint4* pl = reinterpret_cast<uint4*>(gl + base);
    ph[0] = make_uint4(hw[0], hw[1], hw[2], hw[3]);
    ph[1] = make_uint4(hw[4], hw[5], hw[6], hw[7]);
    pl[0] = make_uint4(lw[0], lw[1], lw[2], lw[3]);
    pl[1] = make_uint4(lw[4], lw[5], lw[6], lw[7]);
}

__global__ void transform_kernel(const float* __restrict__ q,
                                 const float* __restrict__ k,
                                 const float* __restrict__ v) {
    int t = blockIdx.x * blockDim.x + threadIdx.x;
    if (t >= B_ * H_ * N_ * 4) return;
    int qd  = t & 3;
    int idx = t >> 2;
    int n = idx % N_;
    int b = idx / (H_ * N_);
    long base = (long)idx * C_ + qd * 16;

    float xq[16], xk[16], xv[16];
#pragma unroll
    for (int i = 0; i < 4; i++) {
        float4 a;
        a = reinterpret_cast<const float4*>(q + base)[i];
        xq[4*i] = a.x; xq[4*i+1] = a.y; xq[4*i+2] = a.z; xq[4*i+3] = a.w;
        a = reinterpret_cast<const float4*>(k + base)[i];
        xk[4*i] = a.x; xk[4*i+1] = a.y; xk[4*i+2] = a.z; xk[4*i+3] = a.w;
        a = reinterpret_cast<const float4*>(v + base)[i];
        xv[4*i] = a.x; xv[4*i+1] = a.y; xv[4*i+2] = a.z; xv[4*i+3] = a.w;
    }
    if (qd > 0) {
        long fb = (long)(b * N_ + n) * 16;
        float mi[16], ml[16];
#pragma unroll
        for (int i = 0; i < 16; i++) { mi[i] = g_inv[fb + i]; ml[i] = g_linv[fb + i]; }
#pragma unroll
        for (int vv = 0; vv < 4; vv++) {
            rot4(xq + 4*vv, mi);
            rot4(xk + 4*vv, ml);
            rot4(xv + 4*vv, mi);
        }
    }
    // fold (1/sqrt(C)) * log2(e) into q so softmax can use exp2
    const float QSCALE = 0.125f * 1.4426950408889634f;
#pragma unroll
    for (int i = 0; i < 16; i++) xq[i] *= QSCALE;

    store_hilo(g_qh, g_ql, base, xq);
    store_hilo(g_kh, g_kl, base, xk);
    store_hilo(g_vh, g_vl, base, xv);
}

// ============================ kernel 3: pipelined mma.sync flash attention ============================
// smem: Q hi/lo 2x8KB, then two 32KB KV stages (KH,KL,VH,VL @ 8KB each)
static constexpr int SQH = 0;
static constexpr int SQL = 8192;
static constexpr int SSTG = 16384;          // stage s at SSTG + s*32768
static constexpr int STG_SZ = 32768;
static constexpr int OKH = 0, OKL = 8192, OVH = 16384, OVL = 24576;
static constexpr int SMEM_TOTAL = 81920;
static constexpr int OF_PITCH = 72;

// async-copy one [64 x 64 bf16] row-major tile (8KB) into SW128-swizzled smem
__device__ __forceinline__ void cpa_tile(uint32_t sdst, const __nv_bfloat16* __restrict__ g, int tid) {
    const char* gp = reinterpret_cast<const char*>(g);
#pragma unroll
    for (int i = 0; i < 4; i++) {
        uint32_t byte = (uint32_t)((i * 128 + tid) * 16);
        CP_ASYNC16(sdst + swz(byte), gp + byte);
    }
}

__global__ void __launch_bounds__(128) attn_kernel(const float* __restrict__ lframes,
                                                   float* __restrict__ out) {
    extern __shared__ char smem[];
    const uint32_t sb = smem_u32(smem);
    const int tid  = threadIdx.x;
    const int warp = tid >> 5;
    const int lane = tid & 31;
    const int qt = blockIdx.x;          // 0..7
    const int bh = blockIdx.y;          // 0..255
    const int b  = bh >> 3;
    const long base = (long)bh * (N_ * C_);
    const int q0 = qt * 64;

    // prologue: async Q tiles (group), then chunk 0 (group)
    cpa_tile(sb + SQH, g_qh + base + (long)q0 * C_, tid);
    cpa_tile(sb + SQL, g_ql + base + (long)q0 * C_, tid);
    CP_COMMIT();
    {
        const long kb = base;  // chunk 0
        uint32_t st0 = sb + SSTG;
        cpa_tile(st0 + OKH, g_kh + kb, tid);
        cpa_tile(st0 + OKL, g_kl + kb, tid);
        cpa_tile(st0 + OVH, g_vh + kb, tid);
        cpa_tile(st0 + OVL, g_vl + kb, tid);
        CP_COMMIT();
    }

    // wait for Q (leave chunk0 possibly in flight: wait_group 1)
    CP_WAIT(1);
    __syncthreads();

    uint32_t qh[4][4], ql[4][4];
    {
        uint32_t row = (uint32_t)(warp * 16 + (lane & 15));
        uint32_t ch  = (uint32_t)((lane >> 4) * 16);
#pragma unroll
        for (int kc = 0; kc < 4; kc++) {
            uint32_t off = swz(row * 128 + kc * 32 + ch);
            ldsm4(qh[kc], sb + SQH + off);
            ldsm4(ql[kc], sb + SQL + off);
        }
    }

    float ot[8][4];
#pragma unroll
    for (int j = 0; j < 8; j++)
#pragma unroll
        for (int e = 0; e < 4; e++) ot[j][e] = 0.0f;
    float m0 = -1e30f, m1 = -1e30f, l0 = 0.0f, l1 = 0.0f;

    const uint32_t k_nb = (uint32_t)(lane >> 4);
    const uint32_t k_kh = (uint32_t)((lane >> 3) & 1);
    const uint32_t k_l7 = (uint32_t)(lane & 7);

    for (int kc = 0; kc < 8; kc++) {
        // prefetch next chunk into the other stage
        if (kc < 7) {
            const long kb = base + (long)(kc + 1) * 64 * C_;
            uint32_t stn = sb + SSTG + ((kc + 1) & 1) * STG_SZ;
            cpa_tile(stn + OKH, g_kh + kb, tid);
            cpa_tile(stn + OKL, g_kl + kb, tid);
            cpa_tile(stn + OVH, g_vh + kb, tid);
            cpa_tile(stn + OVL, g_vl + kb, tid);
            CP_COMMIT();
            CP_WAIT(1);
        } else {
            CP_WAIT(0);
        }
        __syncthreads();
        const uint32_t stg = sb + SSTG + (kc & 1) * STG_SZ;

        // ---- GEMM1: S = Qh*Kh^T + Qh*Kl^T + Ql*Kh^T ----
        float st[8][4];
#pragma unroll
        for (int j = 0; j < 8; j++)
#pragma unroll
            for (int e = 0; e < 4; e++) st[j][e] = 0.0f;

#pragma unroll
        for (int kcc = 0; kcc < 4; kcc++) {
#pragma unroll
            for (int np = 0; np < 4; np++) {
                uint32_t key = (uint32_t)(np * 16) + k_nb * 8 + k_l7;
                uint32_t off = swz(key * 128 + (uint32_t)(kcc * 32) + k_kh * 16);
                uint32_t bh4[4], bl4[4];
                ldsm4(bh4, stg + OKH + off);
                ldsm4(bl4, stg + OKL + off);
                mma16816(st[2*np],   qh[kcc], bh4);
                mma16816(st[2*np+1], qh[kcc], bh4 + 2);
                mma16816(st[2*np],   qh[kcc], bl4);
                mma16816(st[2*np+1], qh[kcc], bl4 + 2);
                mma16816(st[2*np],   ql[kcc], bh4);
                mma16816(st[2*np+1], ql[kcc], bh4 + 2);
            }
        }

        // ---- online softmax (base-2 domain) ----
        float mx0 = st[0][0], mx1 = st[0][2];
#pragma unroll
        for (int j = 0; j < 8; j++) {
            mx0 = fmaxf(mx0, fmaxf(st[j][0], st[j][1]));
            mx1 = fmaxf(mx1, fmaxf(st[j][2], st[j][3]));
        }
#pragma unroll
        for (int o = 1; o <= 2; o <<= 1) {
            mx0 = fmaxf(mx0, __shfl_xor_sync(0xffffffffu, mx0, o));
            mx1 = fmaxf(mx1, __shfl_xor_sync(0xffffffffu, mx1, o));
        }
        float mn0 = fmaxf(m0, mx0), mn1 = fmaxf(m1, mx1);
        float a0 = ex2f(m0 - mn0), a1 = ex2f(m1 - mn1);
        m0 = mn0; m1 = mn1;

        uint32_t pH[8][2], pL[8][2];
        float s0 = 0.0f, s1 = 0.0f;
#pragma unroll
        for (int j = 0; j < 8; j++) {
            float p00 = ex2f(st[j][0] - m0);
            float p01 = ex2f(st[j][1] - m0);
            float p10 = ex2f(st[j][2] - m1);
            float p11 = ex2f(st[j][3] - m1);
            s0 += p00 + p01; s1 += p10 + p11;
            __nv_bfloat16 h00 = __float2bfloat16_rn(p00);
            __nv_bfloat16 h01 = __float2bfloat16_rn(p01);
            __nv_bfloat16 h10 = __float2bfloat16_rn(p10);
            __nv_bfloat16 h11 = __float2bfloat16_rn(p11);
            pH[j][0] = (uint32_t)__bfloat16_as_ushort(h00) | ((uint32_t)__bfloat16_as_ushort(h01) << 16);
            pH[j][1] = (uint32_t)__bfloat16_as_ushort(h10) | ((uint32_t)__bfloat16_as_ushort(h11) << 16);
            pL[j][0] = pack_bf16x2(p00 - __bfloat162float(h00), p01 - __bfloat162float(h01));
            pL[j][1] = pack_bf16x2(p10 - __bfloat162float(h10), p11 - __bfloat162float(h11));
        }
#pragma unroll
        for (int o = 1; o <= 2; o <<= 1) {
            s0 += __shfl_xor_sync(0xffffffffu, s0, o);
            s1 += __shfl_xor_sync(0xffffffffu, s1, o);
        }
        l0 = l0 * a0 + s0;
        l1 = l1 * a1 + s1;
#pragma unroll
        for (int j = 0; j < 8; j++) {
            ot[j][0] *= a0; ot[j][1] *= a0;
            ot[j][2] *= a1; ot[j][3] *= a1;
        }

        // ---- GEMM2: O += Ph*Vh + Ph*Vl + Pl*Vh ----
#pragma unroll
        for (int ks = 0; ks < 4; ks++) {
            uint32_t aH[4] = {pH[2*ks][0], pH[2*ks][1], pH[2*ks+1][0], pH[2*ks+1][1]};
            uint32_t aL[4] = {pL[2*ks][0], pL[2*ks][1], pL[2*ks+1][0], pL[2*ks+1][1]};
            uint32_t vrow = (uint32_t)(ks * 16) + k_kh * 8 + k_l7;
#pragma unroll
            for (int np = 0; np < 4; np++) {
                uint32_t off = swz(vrow * 128 + (uint32_t)(np * 32) + k_nb * 16);
                uint32_t bh4[4], bl4[4];
                ldsm4t(bh4, stg + OVH + off);
                ldsm4t(bl4, stg + OVL + off);
                mma16816(ot[2*np],   aH, bh4);
                mma16816(ot[2*np+1], aH, bh4 + 2);
                mma16816(ot[2*np],   aH, bl4);
                mma16816(ot[2*np+1], aH, bl4 + 2);
                mma16816(ot[2*np],   aL, bh4);
                mma16816(ot[2*np+1], aL, bh4 + 2);
            }
        }
        __syncthreads();   // all warps done reading this stage before it is overwritten
    }

    // ---- epilogue: normalize, roundtrip via smem, fused frame transform ----
    float* Of = reinterpret_cast<float*>(smem + SSTG);   // [64][OF_PITCH]
    {
        float inv0 = 1.0f / l0, inv1 = 1.0f / l1;
        int r0 = warp * 16 + (lane >> 2);
        int r1 = r0 + 8;
        int cb = 2 * (lane & 3);
#pragma unroll
        for (int j = 0; j < 8; j++) {
            int col = j * 8 + cb;
            *reinterpret_cast<float2*>(Of + r0 * OF_PITCH + col) =
                make_float2(ot[j][0] * inv0, ot[j][1] * inv0);
            *reinterpret_cast<float2*>(Of + r1 * OF_PITCH + col) =
                make_float2(ot[j][2] * inv1, ot[j][3] * inv1);
        }
    }
    __syncthreads();

#pragma unroll
    for (int it = 0; it < 8; it++) {
        int task = it * 128 + tid;      // 0..1023
        int rr = task >> 4;
        int g  = task & 15;
        const float* src = Of + rr * OF_PITCH + g * 4;
        float x0 = src[0], x1 = src[1], x2 = src[2], x3 = src[3];
        float y0, y1, y2, y3;
        if (g < 4) {
            y0 = x0; y1 = x1; y2 = x2; y3 = x3;
        } else {
            const float* M = lframes + (long)(b * N_ + q0 + rr) * 16;
            y0 = M[0]  * x0 + M[1]  * x1 + M[2]  * x2 + M[3]  * x3;
            y1 = M[4]  * x0 + M[5]  * x1 + M[6]  * x2 + M[7]  * x3;
            y2 = M[8]  * x0 + M[9]  * x1 + M[10] * x2 + M[11] * x3;
            y3 = M[12] * x0 + M[13] * x1 + M[14] * x2 + M[15] * x3;
        }
        *reinterpret_cast<float4*>(out + base + (long)(q0 + rr) * C_ + g * 4) =
            make_float4(y0, y1, y2, y3);
    }
}

// ---------------------------------------------------------------------------
extern "C" void kernel_launch(void* const* d_in, const int* in_sizes, int n_in,
                              void* d_out, int out_size) {
    const float* big[3] = {nullptr, nullptr, nullptr};
    const float* lf = nullptr;
    int nb = 0;
    for (int i = 0; i < n_in; i++) {
        if (in_sizes[i] == FR_ELEMS && lf == nullptr) lf = (const float*)d_in[i];
        else if (nb < 3) big[nb++] = (const float*)d_in[i];
    }
    const float* q = big[0];
    const float* k = big[1];
    const float* v = big[2];
    float* out = (float*)d_out;

    frames_kernel<<<(B_ * N_ + 255) / 256, 256>>>(lf);
    transform_kernel<<<(B_ * H_ * N_ * 4 + 255) / 256, 256>>>(q, k, v);

    cudaFuncSetAttribute(attn_kernel, cudaFuncAttributeMaxDynamicSharedMemorySize, SMEM_TOTAL);
    attn_kernel<<<dim3(8, 256), 128, SMEM_TOTAL>>>(lf, out);
}